// round 5
// baseline (speedup 1.0000x reference)
#include <cuda_runtime.h>
#include <cuda_bf16.h>
#include <cstdint>
#include <cstddef>

#define BB 16
#define SS 8192
#define DD 192
#define NH 16
#define MTOT (BB*SS)   // 131072

// ---------------- scratch (device globals; allocations are forbidden) ----------------
// attention output, pre-split bf16 hi/lo packed 2/word: [row][96 words]
__device__ __align__(16) uint32_t g_ah[(size_t)MTOT * 96];
__device__ __align__(16) uint32_t g_al[(size_t)MTOT * 96];
// weights: 4 mats (q=0,k=1,v=2,o=3) x 192 rows x 96 words, bf16 hi/lo
__device__ __align__(16) uint32_t g_wh[4 * 192 * 96];
__device__ __align__(16) uint32_t g_wl[4 * 192 * 96];

// ---------------- helpers ----------------
__device__ __forceinline__ uint32_t pack2(float a, float b) {
    __nv_bfloat162 t = __floats2bfloat162_rn(a, b);
    return reinterpret_cast<uint32_t&>(t);
}
__device__ __forceinline__ void split2(float a, float b, uint32_t& h, uint32_t& l) {
    float ah = __bfloat162float(__float2bfloat16_rn(a));
    float bh = __bfloat162float(__float2bfloat16_rn(b));
    h = pack2(ah, bh);
    l = pack2(a - ah, b - bh);
}
__device__ __forceinline__ void mma16(float* c, const uint32_t a[4], uint32_t b0, uint32_t b1) {
    asm volatile("mma.sync.aligned.m16n8k16.row.col.f32.bf16.bf16.f32 "
        "{%0,%1,%2,%3}, {%4,%5,%6,%7}, {%8,%9}, {%0,%1,%2,%3};"
        : "+f"(c[0]), "+f"(c[1]), "+f"(c[2]), "+f"(c[3])
        : "r"(a[0]), "r"(a[1]), "r"(a[2]), "r"(a[3]), "r"(b0), "r"(b1));
}
__device__ __forceinline__ void ldsm4(uint32_t* r, uint32_t saddr) {
    asm volatile("ldmatrix.sync.aligned.m8n8.x4.shared.b16 {%0,%1,%2,%3}, [%4];"
        : "=r"(r[0]), "=r"(r[1]), "=r"(r[2]), "=r"(r[3]) : "r"(saddr));
}
__device__ __forceinline__ void ldsm2(uint32_t* r, uint32_t saddr) {
    asm volatile("ldmatrix.sync.aligned.m8n8.x2.shared.b16 {%0,%1}, [%2];"
        : "=r"(r[0]), "=r"(r[1]) : "r"(saddr));
}
__device__ __forceinline__ void cpa16(uint32_t saddr, const void* g) {
    asm volatile("cp.async.cg.shared.global [%0], [%1], 16;" :: "r"(saddr), "l"(g));
}

// =====================================================================================
// split_w: pre-split all 4 weight matrices into bf16 hi/lo
// =====================================================================================
__global__ __launch_bounds__(256) void k_split_w(
    const float* __restrict__ Wq, const float* __restrict__ Wk,
    const float* __restrict__ Wv, const float* __restrict__ Wo) {
    int f = blockIdx.x * 256 + threadIdx.x;   // < 4*9216
    int mat = f / 9216, g = f - mat * 9216;
    const float* W = (mat == 0) ? Wq : (mat == 1) ? Wk : (mat == 2) ? Wv : Wo;
    float4 v = ((const float4*)W)[g];
    uint32_t h0, l0, h1, l1;
    split2(v.x, v.y, h0, l0);
    split2(v.z, v.w, h1, l1);
    ((uint2*)g_wh)[f] = make_uint2(h0, h1);
    ((uint2*)g_wl)[f] = make_uint2(l0, l1);
}

// =====================================================================================
// k_fused: per 64-row tile, computes Q,K,V (80-row A tile with halo) via bf16x3
// mma.sync, keeps them in smem, runs banded softmax+PV, writes pre-split attn out.
//
// smem word map (4B words):
//   A_hi [0,8000)       80 rows x stride 100 (96 used)
//   A_lo [8000,16000)
//   B ring [16000,25216): 4 x 2304 (Bh0, Bl0, Bh1, Bl1), stride 12/row, k16 chunk
//   K    [25216,38544)   68 rows (global m0-2..m0+65) x stride 196, fp32
//   V    [38544,51872)
//   bias [51872,52448)   bk | bv | bq
//   Q overwrites A region after the Q GEMM: 64 rows x stride 196.
// =====================================================================================
#define A_LO   8000
#define BBASE  16000
#define KBASE  25216
#define VBASE  38544
#define PBASE  51872
#define FUSED_SMEM (52448 * 4)

__global__ __launch_bounds__(256, 1) void k_fused(
    const float* __restrict__ x, const float* __restrict__ mask0,
    const float* __restrict__ bq, const float* __restrict__ bk,
    const float* __restrict__ bv)
{
    extern __shared__ __align__(16) uint32_t sm[];
    float* sf = (float*)sm;
    const uint32_t smb = (uint32_t)__cvta_generic_to_shared(sm);
    const int tid = threadIdx.x;
    const int warp = tid >> 5, lane = tid & 31;
    const int lr = lane >> 2, lc = lane & 3;
    const int group = lane >> 3, lrow = lane & 7;
    const int m0 = blockIdx.x * 64;
    const int n0 = warp * 24;           // warp grid 1(M) x 8(N): each warp n in [24w, 24w+24)

    // ---- params ----
    if (tid < 192) {
        sf[PBASE + tid]       = bk[tid];
        sf[PBASE + 192 + tid] = bv[tid];
        sf[PBASE + 384 + tid] = bq[tid];
    }

    // ---- stage A: x rows [m0-8, m0+72), fp32 -> bf16 hi/lo, stride 100 words ----
    #pragma unroll
    for (int it = 0; it < 15; it++) {
        int id = it * 256 + tid;          // < 3840 = 80*48
        int r = id / 48, f4 = id - r * 48;
        int gr = m0 - 8 + r;
        gr = (gr < 0) ? 0 : (gr >= MTOT ? MTOT - 1 : gr);
        float4 v = *(const float4*)(x + (size_t)gr * DD + f4 * 4);
        uint32_t h0, l0, h1, l1;
        split2(v.x, v.y, h0, l0);
        split2(v.z, v.w, h1, l1);
        *(uint2*)(sm + r * 100 + 2 * f4)        = make_uint2(h0, h1);
        *(uint2*)(sm + A_LO + r * 100 + 2 * f4) = make_uint2(l0, l1);
    }
    __syncthreads();

    float acc[5][3][4];

    auto stageB = [&](const uint32_t* Wh, const uint32_t* Wl, int kc, int buf) {
        const uint32_t bb = BBASE + buf * 4608;
        #pragma unroll
        for (int i = 0; i < 3; i++) {
            int id = i * 256 + tid;       // < 768
            int half = id >= 384;
            int jj = id - (half ? 384 : 0);
            int r = jj >> 1, u = jj & 1;
            const uint32_t* src = (half ? Wl : Wh) + r * 96 + kc * 8 + u * 4;
            cpa16(smb + (bb + (half ? 2304 : 0) + r * 12 + u * 4) * 4, src);
        }
        asm volatile("cp.async.commit_group;");
    };

    auto compute = [&](int kc, int buf) {
        const uint32_t bb = BBASE + buf * 4608;
        uint32_t ah[5][4], al[5][4];
        #pragma unroll
        for (int tm = 0; tm < 5; tm++) {
            uint32_t adr = smb + ((tm * 16 + lrow + ((group & 1) << 3)) * 100
                                  + kc * 8 + ((group >> 1) << 2)) * 4;
            ldsm4(ah[tm], adr);
            ldsm4(al[tm], adr + A_LO * 4);
        }
        uint32_t bh[6], bl[6];
        {
            uint32_t adr = smb + (bb + (n0 + lrow + ((group >> 1) << 3)) * 12
                                  + ((group & 1) << 2)) * 4;
            ldsm4(bh, adr);
            ldsm4(bl, adr + 2304 * 4);
            uint32_t adr2 = smb + (bb + (n0 + 16 + lrow) * 12 + ((group & 1) << 2)) * 4;
            ldsm2(bh + 4, adr2);
            ldsm2(bl + 4, adr2 + 2304 * 4);
        }
        #pragma unroll
        for (int tm = 0; tm < 5; tm++)
            #pragma unroll
            for (int n = 0; n < 3; n++) {
                mma16(acc[tm][n], ah[tm], bl[2 * n], bl[2 * n + 1]);
                mma16(acc[tm][n], al[tm], bh[2 * n], bh[2 * n + 1]);
                mma16(acc[tm][n], ah[tm], bh[2 * n], bh[2 * n + 1]);
            }
    };

    auto gemm = [&](const uint32_t* Wh, const uint32_t* Wl, uint32_t resBase,
                    int rShift, int rCount, const float* bias, float scale) {
        #pragma unroll
        for (int a = 0; a < 5; a++)
            #pragma unroll
            for (int b = 0; b < 3; b++)
                #pragma unroll
                for (int c = 0; c < 4; c++) acc[a][b][c] = 0.f;

        stageB(Wh, Wl, 0, 0);
        stageB(Wh, Wl, 1, 1);
        #pragma unroll 1
        for (int kc = 0; kc < 12; kc++) {
            if (kc < 11) asm volatile("cp.async.wait_group 1;" ::: "memory");
            else         asm volatile("cp.async.wait_group 0;" ::: "memory");
            __syncthreads();
            compute(kc, kc & 1);
            __syncthreads();
            if (kc < 10) stageB(Wh, Wl, kc + 2, kc & 1);
        }
        // epilogue: result rows rA - rShift, + bias, * scale
        #pragma unroll
        for (int tm = 0; tm < 5; tm++)
            #pragma unroll
            for (int n = 0; n < 3; n++) {
                int col = n0 + n * 8 + 2 * lc;
                float b0 = bias[col], b1 = bias[col + 1];
                int r0 = tm * 16 + lr - rShift;
                int r1 = r0 + 8;
                if ((unsigned)r0 < (unsigned)rCount)
                    *(float2*)(sf + resBase + r0 * 196 + col) =
                        make_float2((acc[tm][n][0] + b0) * scale,
                                    (acc[tm][n][1] + b1) * scale);
                if ((unsigned)r1 < (unsigned)rCount)
                    *(float2*)(sf + resBase + r1 * 196 + col) =
                        make_float2((acc[tm][n][2] + b0) * scale,
                                    (acc[tm][n][3] + b1) * scale);
            }
    };

    // K (mat 1), V (mat 2), then Q (mat 0; result overwrites A region)
    gemm(g_wh + 1 * 18432, g_wl + 1 * 18432, KBASE, 6, 68, sf + PBASE,       1.0f);
    gemm(g_wh + 2 * 18432, g_wl + 2 * 18432, VBASE, 6, 68, sf + PBASE + 192, 1.0f);
    gemm(g_wh + 0 * 18432, g_wl + 0 * 18432, 0,     8, 64, sf + PBASE + 384,
         0.28867513459481287f);
    __syncthreads();

    // ---- banded attention, 64 rows x 16 heads; 4 tasks/thread ----
    const float NEGINF = __int_as_float(0xff800000);
    #pragma unroll
    for (int jt = 0; jt < 4; jt++) {
        int id = jt * 256 + tid;
        int row = id >> 4, h = id & 15;
        int m = m0 + row;
        int i = m & (SS - 1);
        int b = m >> 13;

        const float* qp = sf + row * 196 + h * 12;
        float q[12];
        #pragma unroll
        for (int j = 0; j < 3; j++) {
            float4 t = *(const float4*)(qp + 4 * j);
            q[4*j] = t.x; q[4*j+1] = t.y; q[4*j+2] = t.z; q[4*j+3] = t.w;
        }

        float sc[5];
        bool val[5];
        #pragma unroll
        for (int dd = 0; dd < 5; dd++) {
            int d = dd - 2;
            int ik = i + d;
            bool v = (ik >= 0) && (ik < SS);
            val[dd] = v;
            float s = NEGINF;
            if (v) {
                const float* kp = sf + KBASE + (row + dd) * 196 + h * 12;
                float a = 0.f;
                #pragma unroll
                for (int j = 0; j < 3; j++) {
                    float4 t = *(const float4*)(kp + 4 * j);
                    a += q[4*j] * t.x + q[4*j+1] * t.y + q[4*j+2] * t.z + q[4*j+3] * t.w;
                }
                float mk = mask0[b * SS + ik];
                s = a + ((mk != 0.f) ? -3.402823466e38f : 0.f);
            }
            sc[dd] = s;
        }
        float mx = sc[0];
        #pragma unroll
        for (int dd = 1; dd < 5; dd++) mx = fmaxf(mx, sc[dd]);
        float p[5], sum = 0.f;
        #pragma unroll
        for (int dd = 0; dd < 5; dd++) { p[dd] = __expf(sc[dd] - mx); sum += p[dd]; }
        float inv = 1.f / sum;
        if (mask0[b * SS + i] < 0.f) inv = 0.f;

        float ctx[12];
        #pragma unroll
        for (int j = 0; j < 12; j++) ctx[j] = 0.f;
        #pragma unroll
        for (int dd = 0; dd < 5; dd++) {
            if (val[dd]) {
                const float* vp = sf + VBASE + (row + dd) * 196 + h * 12;
                #pragma unroll
                for (int j = 0; j < 3; j++) {
                    float4 t = *(const float4*)(vp + 4 * j);
                    ctx[4*j]   += p[dd] * t.x;
                    ctx[4*j+1] += p[dd] * t.y;
                    ctx[4*j+2] += p[dd] * t.z;
                    ctx[4*j+3] += p[dd] * t.w;
                }
            }
        }
        size_t ow = (size_t)m * 96 + h * 6;
        #pragma unroll
        for (int j = 0; j < 6; j++) {
            uint32_t hw, lw;
            split2(ctx[2*j] * inv, ctx[2*j+1] * inv, hw, lw);
            g_ah[ow + j] = hw;
            g_al[ow + j] = lw;
        }
    }
}

// =====================================================================================
// k_out (R2, proven): out = LN(attn @ Wo^T + bo + x). CTA 64 x 192, K-tile 48.
// =====================================================================================
__global__ __launch_bounds__(256, 2) void k_out(
    const float* __restrict__ x, const float* __restrict__ bo,
    const float* __restrict__ lng, const float* __restrict__ lnb,
    float* __restrict__ out)
{
    extern __shared__ uint32_t sm[];
    const uint32_t smbase = (uint32_t)__cvta_generic_to_shared(sm);
    const int tid = threadIdx.x;
    const int m0 = blockIdx.x * 64;
    const int warp = tid >> 5, lane = tid & 31;
    const int wm = (warp >> 2) * 32, wn = (warp & 3) * 48;
    const int lr = lane >> 2, lc = lane & 3;
    const int group = lane >> 3, lrow = lane & 7;
    const int aoff = (lrow + ((group & 1) << 3)) * 28 + ((group >> 1) << 2);
    const int boff = (lrow + ((group >> 1) << 3)) * 28 + ((group & 1) << 2);
    const uint32_t* Wh = g_wh + 3 * 18432;
    const uint32_t* Wl = g_wl + 3 * 18432;

    float acc[2][6][4];
    #pragma unroll
    for (int a = 0; a < 2; a++)
        #pragma unroll
        for (int b = 0; b < 6; b++)
            #pragma unroll
            for (int c = 0; c < 4; c++) acc[a][b][c] = 0.f;

    auto stage = [&](int kt, int buf) {
        const int kw0 = kt * 24;
        const uint32_t base = buf * 14336;
        #pragma unroll
        for (int i = 0; i < 3; i++) {
            int id = i * 256 + tid;
            int half = id >= 384;
            int j = id - (half ? 384 : 0);
            int r = j / 6, u = j - r * 6;
            const uint32_t* src = (half ? g_al : g_ah) + (size_t)(m0 + r) * 96 + kw0 + u * 4;
            uint32_t sa = smbase + (base + (half ? 1792 : 0) + r * 28 + u * 4) * 4;
            cpa16(sa, src);
        }
        #pragma unroll
        for (int i = 0; i < 9; i++) {
            int id = i * 256 + tid;
            int half = id >= 1152;
            int j = id - (half ? 1152 : 0);
            int r = j / 6, u = j - r * 6;
            const uint32_t* src = (half ? Wl : Wh) + r * 96 + kw0 + u * 4;
            uint32_t sa = smbase + (base + 3584 + (half ? 5376 : 0) + r * 28 + u * 4) * 4;
            cpa16(sa, src);
        }
        asm volatile("cp.async.commit_group;");
    };

    auto compute = [&](int buf) {
        const uint32_t base = buf * 14336;
        #pragma unroll
        for (int s = 0; s < 3; s++) {
            const int kw = s * 8;
            uint32_t ah[2][4], al[2][4];
            #pragma unroll
            for (int im = 0; im < 2; im++) {
                uint32_t adr = smbase + (base + (wm + im * 16) * 28 + kw + aoff) * 4;
                ldsm4(ah[im], adr);
                ldsm4(al[im], adr + 1792 * 4);
            }
            uint32_t bh[3][4], bl[3][4];
            #pragma unroll
            for (int jp = 0; jp < 3; jp++) {
                uint32_t adr = smbase + (base + 3584 + (wn + jp * 16) * 28 + kw + boff) * 4;
                ldsm4(bh[jp], adr);
                ldsm4(bl[jp], adr + 5376 * 4);
            }
            #pragma unroll
            for (int im = 0; im < 2; im++)
                #pragma unroll
                for (int jp = 0; jp < 3; jp++) {
                    mma16(acc[im][2*jp],   ah[im], bl[jp][0], bl[jp][1]);
                    mma16(acc[im][2*jp],   al[im], bh[jp][0], bh[jp][1]);
                    mma16(acc[im][2*jp],   ah[im], bh[jp][0], bh[jp][1]);
                    mma16(acc[im][2*jp+1], ah[im], bl[jp][2], bl[jp][3]);
                    mma16(acc[im][2*jp+1], al[im], bh[jp][2], bh[jp][3]);
                    mma16(acc[im][2*jp+1], ah[im], bh[jp][2], bh[jp][3]);
                }
        }
    };

    stage(0, 0);
    for (int kt = 0; kt < 4; kt++) {
        if (kt < 3) {
            stage(kt + 1, (kt + 1) & 1);
            asm volatile("cp.async.wait_group 1;");
        } else {
            asm volatile("cp.async.wait_group 0;");
        }
        __syncthreads();
        compute(kt & 1);
        __syncthreads();
    }

    // epilogue: h = acc + bo + x -> smem (stride 200 floats), then LN
    float* sh = (float*)sm;
    #pragma unroll
    for (int im = 0; im < 2; im++)
        #pragma unroll
        for (int jn = 0; jn < 6; jn++) {
            int rl = wm + im * 16 + lr;
            int col = wn + jn * 8 + 2 * lc;
            float b0 = bo[col], b1 = bo[col + 1];
            float2 xv0 = *(const float2*)(x + (size_t)(m0 + rl) * DD + col);
            float2 xv1 = *(const float2*)(x + (size_t)(m0 + rl + 8) * DD + col);
            sh[rl * 200 + col]           = acc[im][jn][0] + b0 + xv0.x;
            sh[rl * 200 + col + 1]       = acc[im][jn][1] + b1 + xv0.y;
            sh[(rl + 8) * 200 + col]     = acc[im][jn][2] + b0 + xv1.x;
            sh[(rl + 8) * 200 + col + 1] = acc[im][jn][3] + b1 + xv1.y;
        }
    __syncthreads();

    #pragma unroll
    for (int it = 0; it < 8; it++) {
        int r = it * 8 + warp;
        float v[6]; float sum = 0.f, ssq = 0.f;
        #pragma unroll
        for (int j = 0; j < 6; j++) {
            v[j] = sh[r * 200 + j * 32 + lane];
            sum += v[j];
            ssq += v[j] * v[j];
        }
        #pragma unroll
        for (int o = 16; o > 0; o >>= 1) {
            sum += __shfl_xor_sync(0xffffffffu, sum, o);
            ssq += __shfl_xor_sync(0xffffffffu, ssq, o);
        }
        float mu  = sum * (1.f / 192.f);
        float var = ssq * (1.f / 192.f) - mu * mu;
        float rs  = rsqrtf(fmaxf(var, 0.f) + 1e-12f);
        #pragma unroll
        for (int j = 0; j < 6; j++) {
            int c = j * 32 + lane;
            out[(size_t)(m0 + r) * DD + c] = (v[j] - mu) * rs * lng[c] + lnb[c];
        }
    }
}

// =====================================================================================
extern "C" void kernel_launch(void* const* d_in, const int* in_sizes, int n_in,
                              void* d_out, int out_size)
{
    const float* x    = (const float*)d_in[0];
    const float* mask0= (const float*)d_in[1];
    const float* Wq   = (const float*)d_in[2];
    const float* bq   = (const float*)d_in[3];
    const float* Wk   = (const float*)d_in[4];
    const float* bk   = (const float*)d_in[5];
    const float* Wv   = (const float*)d_in[6];
    const float* bv   = (const float*)d_in[7];
    const float* Wo   = (const float*)d_in[8];
    const float* bo   = (const float*)d_in[9];
    const float* lng  = (const float*)d_in[10];
    const float* lnb  = (const float*)d_in[11];
    float* out = (float*)d_out;

    cudaFuncSetAttribute(k_fused, cudaFuncAttributeMaxDynamicSharedMemorySize, FUSED_SMEM);
    cudaFuncSetAttribute(k_out,   cudaFuncAttributeMaxDynamicSharedMemorySize, 114688);

    k_split_w<<<144, 256>>>(Wq, Wk, Wv, Wo);
    k_fused<<<MTOT / 64, 256, FUSED_SMEM>>>(x, mask0, bq, bk, bv);
    k_out<<<MTOT / 64, 256, 114688>>>(x, bo, lng, lnb, out);
}

// round 6
// speedup vs baseline: 1.3077x; 1.3077x over previous
#include <cuda_runtime.h>
#include <cuda_bf16.h>
#include <cstdint>
#include <cstddef>

#define BB 16
#define SS 8192
#define DD 192
#define NH 16
#define MTOT (BB*SS)   // 131072

// ---------------- scratch (device globals; allocations are forbidden) ----------------
__device__ float g_q[(size_t)MTOT * DD];
__device__ float g_k[(size_t)MTOT * DD];
__device__ float g_v[(size_t)MTOT * DD];
// attention output, pre-split bf16 hi/lo packed 2/word: [row][96 words]
__device__ __align__(16) uint32_t g_ah[(size_t)MTOT * 96];
__device__ __align__(16) uint32_t g_al[(size_t)MTOT * 96];
// weights: 4 mats (q=0,k=1,v=2,o=3) x 192 rows x 96 words, bf16 hi/lo
__device__ __align__(16) uint32_t g_wh[4 * 192 * 96];
__device__ __align__(16) uint32_t g_wl[4 * 192 * 96];

// ---------------- helpers ----------------
__device__ __forceinline__ uint32_t pack2(float a, float b) {
    __nv_bfloat162 t = __floats2bfloat162_rn(a, b);
    return reinterpret_cast<uint32_t&>(t);
}
__device__ __forceinline__ void split2(float a, float b, uint32_t& h, uint32_t& l) {
    float ah = __bfloat162float(__float2bfloat16_rn(a));
    float bh = __bfloat162float(__float2bfloat16_rn(b));
    h = pack2(ah, bh);
    l = pack2(a - ah, b - bh);
}
__device__ __forceinline__ void mma16(float* c, const uint32_t a[4], uint32_t b0, uint32_t b1) {
    asm volatile("mma.sync.aligned.m16n8k16.row.col.f32.bf16.bf16.f32 "
        "{%0,%1,%2,%3}, {%4,%5,%6,%7}, {%8,%9}, {%0,%1,%2,%3};"
        : "+f"(c[0]), "+f"(c[1]), "+f"(c[2]), "+f"(c[3])
        : "r"(a[0]), "r"(a[1]), "r"(a[2]), "r"(a[3]), "r"(b0), "r"(b1));
}
__device__ __forceinline__ void ldsm4(uint32_t* r, uint32_t saddr) {
    asm volatile("ldmatrix.sync.aligned.m8n8.x4.shared.b16 {%0,%1,%2,%3}, [%4];"
        : "=r"(r[0]), "=r"(r[1]), "=r"(r[2]), "=r"(r[3]) : "r"(saddr));
}
__device__ __forceinline__ void cpa16(uint32_t saddr, const void* g) {
    asm volatile("cp.async.cg.shared.global [%0], [%1], 16;" :: "r"(saddr), "l"(g));
}

// smem word offsets (4-byte words) for the GEMM kernels:
//   A_hi [0,12800)        128 rows x stride 100 (96 used)
//   A_lo [12800,25600)
//   B ring [25600,47104)  2 buffers x (hi 192x28 | lo 192x28) = 2 x 10752 words
#define A_LO_W   12800
#define B_BASE_W 25600
#define B_BUF_W  10752
#define B_HALF_W 5376
#define GEMM_SMEM (47104 * 4)   // 188416 bytes

// =====================================================================================
// split_w: pre-split all 4 weight matrices into bf16 hi/lo
// =====================================================================================
__global__ __launch_bounds__(256) void k_split_w(
    const float* __restrict__ Wq, const float* __restrict__ Wk,
    const float* __restrict__ Wv, const float* __restrict__ Wo) {
    int f = blockIdx.x * 256 + threadIdx.x;   // < 4*9216
    int mat = f / 9216, g = f - mat * 9216;
    const float* W = (mat == 0) ? Wq : (mat == 1) ? Wk : (mat == 2) ? Wv : Wo;
    float4 v = ((const float4*)W)[g];
    uint32_t h0, l0, h1, l1;
    split2(v.x, v.y, h0, l0);
    split2(v.z, v.w, h1, l1);
    ((uint2*)g_wh)[f] = make_uint2(h0, h1);
    ((uint2*)g_wl)[f] = make_uint2(l0, l1);
}

// =====================================================================================
// Shared GEMM compute step (warp grid 2(M) x 4(N), warp tile 64x48).
// A resident (stride 100 words), B double-buffered (stride 28 words, 24-word ktile).
// =====================================================================================
struct GemmCtx {
    uint32_t smb;
    int wm, wn, lr, lc, aoff, boff;
};

__device__ __forceinline__ void gemm_compute(
    const GemmCtx& g, float acc[4][6][4], int kt, int buf)
{
    #pragma unroll
    for (int c = 0; c < 3; c++) {
        uint32_t ah[4][4], al[4][4];
        #pragma unroll
        for (int tm = 0; tm < 4; tm++) {
            uint32_t adr = g.smb + ((g.wm + tm * 16) * 100 + kt * 24 + c * 8 + g.aoff) * 4;
            ldsm4(ah[tm], adr);
            ldsm4(al[tm], adr + A_LO_W * 4);
        }
        uint32_t bh[3][4], bl[3][4];
        #pragma unroll
        for (int jp = 0; jp < 3; jp++) {
            uint32_t adr = g.smb + (B_BASE_W + buf * B_BUF_W
                                    + (g.wn + jp * 16) * 28 + c * 8 + g.boff) * 4;
            ldsm4(bh[jp], adr);
            ldsm4(bl[jp], adr + B_HALF_W * 4);
        }
        #pragma unroll
        for (int tm = 0; tm < 4; tm++)
            #pragma unroll
            for (int jp = 0; jp < 3; jp++) {
                mma16(acc[tm][2*jp],   ah[tm], bl[jp][0], bl[jp][1]);
                mma16(acc[tm][2*jp],   al[tm], bh[jp][0], bh[jp][1]);
                mma16(acc[tm][2*jp],   ah[tm], bh[jp][0], bh[jp][1]);
                mma16(acc[tm][2*jp+1], ah[tm], bl[jp][2], bl[jp][3]);
                mma16(acc[tm][2*jp+1], al[tm], bh[jp][2], bh[jp][3]);
                mma16(acc[tm][2*jp+1], ah[tm], bh[jp][2], bh[jp][3]);
            }
    }
}

__device__ __forceinline__ void stageB(
    uint32_t smb, int tid,
    const uint32_t* __restrict__ Wh, const uint32_t* __restrict__ Wl,
    int kt, int buf)
{
    #pragma unroll
    for (int i = 0; i < 9; i++) {
        int id = i * 256 + tid;                 // < 2304
        int half = id >= 1152;
        int j = id - (half ? 1152 : 0);
        int r = j / 6, u = j - r * 6;
        const uint32_t* src = (half ? Wl : Wh) + r * 96 + kt * 24 + u * 4;
        cpa16(smb + (B_BASE_W + buf * B_BUF_W + half * B_HALF_W + r * 28 + u * 4) * 4, src);
    }
    asm volatile("cp.async.commit_group;");
}

// =====================================================================================
// k_qkv: CTA = 128 rows x (q,k,v). A = x rows, split inline, resident full-K.
// 12 steps: sel 0..2 x ktile 0..3, B double-buffered.
// =====================================================================================
__global__ __launch_bounds__(256, 1) void k_qkv(
    const float* __restrict__ x,
    const float* __restrict__ bq, const float* __restrict__ bk,
    const float* __restrict__ bv)
{
    extern __shared__ __align__(16) uint32_t sm[];
    const uint32_t smb = (uint32_t)__cvta_generic_to_shared(sm);
    const int tid = threadIdx.x;
    const int warp = tid >> 5, lane = tid & 31;
    const int m0 = blockIdx.x * 128;
    const int group = lane >> 3, lrow = lane & 7;

    GemmCtx g;
    g.smb = smb;
    g.wm = (warp >> 2) * 64;
    g.wn = (warp & 3) * 48;
    g.lr = lane >> 2;
    g.lc = lane & 3;
    g.aoff = (lrow + ((group & 1) << 3)) * 100 + ((group >> 1) << 2);
    g.boff = (lrow + ((group >> 1) << 3)) * 28 + ((group & 1) << 2);

    // kick off first two B tiles (sel 0, kt 0/1)
    stageB(smb, tid, g_wh, g_wl, 0, 0);
    stageB(smb, tid, g_wh, g_wl, 1, 1);

    // stage A: x rows [m0, m0+128), fp32 -> bf16 hi/lo, resident, stride 100
    #pragma unroll
    for (int it = 0; it < 24; it++) {
        int id = it * 256 + tid;          // < 6144 = 128*48
        int r = id / 48, f4 = id - r * 48;
        float4 v = ((const float4*)x)[(size_t)(m0 + r) * 48 + f4];
        uint32_t h0, l0, h1, l1;
        split2(v.x, v.y, h0, l0);
        split2(v.z, v.w, h1, l1);
        *(uint2*)(sm + r * 100 + 2 * f4)          = make_uint2(h0, h1);
        *(uint2*)(sm + A_LO_W + r * 100 + 2 * f4) = make_uint2(l0, l1);
    }

    float acc[4][6][4];
    const float* biases[3] = {bq, bk, bv};

    #pragma unroll 1
    for (int s = 0; s < 12; s++) {
        const int sel = s >> 2, kt = s & 3;
        if (s < 11) asm volatile("cp.async.wait_group 1;" ::: "memory");
        else        asm volatile("cp.async.wait_group 0;" ::: "memory");
        __syncthreads();
        if (kt == 0) {
            #pragma unroll
            for (int a = 0; a < 4; a++)
                #pragma unroll
                for (int b = 0; b < 6; b++)
                    #pragma unroll
                    for (int c = 0; c < 4; c++) acc[a][b][c] = 0.f;
        }
        gemm_compute(g, acc, kt, s & 1);
        __syncthreads();
        if (s < 10) {
            int s2 = s + 2;
            stageB(smb, tid, g_wh + (s2 >> 2) * 18432, g_wl + (s2 >> 2) * 18432,
                   s2 & 3, s2 & 1);
        }
        if (kt == 3) {
            float* dst = (sel == 0) ? g_q : (sel == 1) ? g_k : g_v;
            const float* bias = biases[sel];
            const float scale = (sel == 0) ? 0.28867513459481287f : 1.0f;
            #pragma unroll
            for (int tm = 0; tm < 4; tm++)
                #pragma unroll
                for (int n = 0; n < 6; n++) {
                    int r = m0 + g.wm + tm * 16 + g.lr;
                    int col = g.wn + n * 8 + 2 * g.lc;
                    float b0 = __ldg(bias + col), b1 = __ldg(bias + col + 1);
                    *(float2*)(dst + (size_t)r * DD + col) =
                        make_float2((acc[tm][n][0] + b0) * scale,
                                    (acc[tm][n][1] + b1) * scale);
                    *(float2*)(dst + (size_t)(r + 8) * DD + col) =
                        make_float2((acc[tm][n][2] + b0) * scale,
                                    (acc[tm][n][3] + b1) * scale);
                }
        }
    }
}

// =====================================================================================
// k_attn: banded attention; writes pre-split bf16 attn (hi/lo packed words).
// =====================================================================================
__global__ __launch_bounds__(256) void k_attn(const float* __restrict__ mask0)
{
    int g = blockIdx.x * 256 + threadIdx.x;
    int m = g >> 4;
    int h = g & 15;
    int i = m & (SS - 1);
    int b = m >> 13;

    const float* qp = g_q + (size_t)m * DD + h * 12;
    float q[12];
    #pragma unroll
    for (int j = 0; j < 3; j++) {
        float4 t = *(const float4*)(qp + 4 * j);
        q[4*j] = t.x; q[4*j+1] = t.y; q[4*j+2] = t.z; q[4*j+3] = t.w;
    }

    const float NEGINF = __int_as_float(0xff800000);
    float sc[5];
    bool val[5];
    #pragma unroll
    for (int dd = 0; dd < 5; dd++) {
        int d = dd - 2;
        int ik = i + d;
        bool v = (ik >= 0) && (ik < SS);
        val[dd] = v;
        float s = NEGINF;
        if (v) {
            const float* kp = g_k + (size_t)(m + d) * DD + h * 12;
            float a = 0.f;
            #pragma unroll
            for (int j = 0; j < 3; j++) {
                float4 t = *(const float4*)(kp + 4 * j);
                a += q[4*j] * t.x + q[4*j+1] * t.y + q[4*j+2] * t.z + q[4*j+3] * t.w;
            }
            float mk = mask0[b * SS + ik];
            s = a + ((mk != 0.f) ? -3.402823466e38f : 0.f);
        }
        sc[dd] = s;
    }
    float mx = sc[0];
    #pragma unroll
    for (int dd = 1; dd < 5; dd++) mx = fmaxf(mx, sc[dd]);
    float p[5], sum = 0.f;
    #pragma unroll
    for (int dd = 0; dd < 5; dd++) { p[dd] = __expf(sc[dd] - mx); sum += p[dd]; }
    float inv = 1.f / sum;
    if (mask0[b * SS + i] < 0.f) inv = 0.f;

    float ctx[12];
    #pragma unroll
    for (int j = 0; j < 12; j++) ctx[j] = 0.f;
    #pragma unroll
    for (int dd = 0; dd < 5; dd++) {
        if (val[dd]) {
            const float* vp = g_v + (size_t)(m + dd - 2) * DD + h * 12;
            #pragma unroll
            for (int j = 0; j < 3; j++) {
                float4 t = *(const float4*)(vp + 4 * j);
                ctx[4*j]   += p[dd] * t.x;
                ctx[4*j+1] += p[dd] * t.y;
                ctx[4*j+2] += p[dd] * t.z;
                ctx[4*j+3] += p[dd] * t.w;
            }
        }
    }
    size_t ow = (size_t)m * 96 + h * 6;
    #pragma unroll
    for (int j = 0; j < 6; j++) {
        uint32_t hw, lw;
        split2(ctx[2*j] * inv, ctx[2*j+1] * inv, hw, lw);
        g_ah[ow + j] = hw;
        g_al[ow + j] = lw;
    }
}

// =====================================================================================
// k_out: out = LN(attn @ Wo^T + bo + x). Same skeleton, 1 sel, 4 steps, fused LN.
// =====================================================================================
__global__ __launch_bounds__(256, 1) void k_out(
    const float* __restrict__ x, const float* __restrict__ bo,
    const float* __restrict__ lng, const float* __restrict__ lnb,
    float* __restrict__ out)
{
    extern __shared__ __align__(16) uint32_t sm[];
    const uint32_t smb = (uint32_t)__cvta_generic_to_shared(sm);
    const int tid = threadIdx.x;
    const int warp = tid >> 5, lane = tid & 31;
    const int m0 = blockIdx.x * 128;
    const int group = lane >> 3, lrow = lane & 7;

    GemmCtx g;
    g.smb = smb;
    g.wm = (warp >> 2) * 64;
    g.wn = (warp & 3) * 48;
    g.lr = lane >> 2;
    g.lc = lane & 3;
    g.aoff = (lrow + ((group & 1) << 3)) * 100 + ((group >> 1) << 2);
    g.boff = (lrow + ((group >> 1) << 3)) * 28 + ((group & 1) << 2);

    // stage A (attn, already split) via cp.async, resident
    #pragma unroll
    for (int i = 0; i < 24; i++) {
        int id = i * 256 + tid;           // < 6144
        int half = id >= 3072;
        int j = id - (half ? 3072 : 0);
        int r = j / 24, u = j - r * 24;
        const uint32_t* src = (half ? g_al : g_ah) + (size_t)(m0 + r) * 96 + u * 4;
        cpa16(smb + (half * A_LO_W + r * 100 + u * 4) * 4, src);
    }
    asm volatile("cp.async.commit_group;");

    const uint32_t* Wh = g_wh + 3 * 18432;
    const uint32_t* Wl = g_wl + 3 * 18432;
    stageB(smb, tid, Wh, Wl, 0, 0);
    stageB(smb, tid, Wh, Wl, 1, 1);

    float acc[4][6][4];
    #pragma unroll
    for (int a = 0; a < 4; a++)
        #pragma unroll
        for (int b = 0; b < 6; b++)
            #pragma unroll
            for (int c = 0; c < 4; c++) acc[a][b][c] = 0.f;

    #pragma unroll 1
    for (int s = 0; s < 4; s++) {
        if (s < 3) asm volatile("cp.async.wait_group 1;" ::: "memory");
        else       asm volatile("cp.async.wait_group 0;" ::: "memory");
        __syncthreads();
        gemm_compute(g, acc, s, s & 1);
        __syncthreads();
        if (s < 2) stageB(smb, tid, Wh, Wl, s + 2, s & 1);
    }

    // epilogue: h = acc + bo + x -> smem (reuse A region, 128 x stride 200)
    float* sh = (float*)sm;
    #pragma unroll
    for (int tm = 0; tm < 4; tm++)
        #pragma unroll
        for (int n = 0; n < 6; n++) {
            int rl = g.wm + tm * 16 + g.lr;
            int col = g.wn + n * 8 + 2 * g.lc;
            float b0 = __ldg(bo + col), b1 = __ldg(bo + col + 1);
            float2 xv0 = *(const float2*)(x + (size_t)(m0 + rl) * DD + col);
            float2 xv1 = *(const float2*)(x + (size_t)(m0 + rl + 8) * DD + col);
            sh[rl * 200 + col]           = acc[tm][n][0] + b0 + xv0.x;
            sh[rl * 200 + col + 1]       = acc[tm][n][1] + b1 + xv0.y;
            sh[(rl + 8) * 200 + col]     = acc[tm][n][2] + b0 + xv1.x;
            sh[(rl + 8) * 200 + col + 1] = acc[tm][n][3] + b1 + xv1.y;
        }
    __syncthreads();

    #pragma unroll 1
    for (int it = 0; it < 16; it++) {
        int r = it * 8 + warp;
        float v[6]; float sum = 0.f, ssq = 0.f;
        #pragma unroll
        for (int j = 0; j < 6; j++) {
            v[j] = sh[r * 200 + j * 32 + lane];
            sum += v[j];
            ssq += v[j] * v[j];
        }
        #pragma unroll
        for (int o = 16; o > 0; o >>= 1) {
            sum += __shfl_xor_sync(0xffffffffu, sum, o);
            ssq += __shfl_xor_sync(0xffffffffu, ssq, o);
        }
        float mu  = sum * (1.f / 192.f);
        float var = ssq * (1.f / 192.f) - mu * mu;
        float rs  = rsqrtf(fmaxf(var, 0.f) + 1e-12f);
        #pragma unroll
        for (int j = 0; j < 6; j++) {
            int c = j * 32 + lane;
            out[(size_t)(m0 + r) * DD + c] = (v[j] - mu) * rs * __ldg(lng + c) + __ldg(lnb + c);
        }
    }
}

// =====================================================================================
extern "C" void kernel_launch(void* const* d_in, const int* in_sizes, int n_in,
                              void* d_out, int out_size)
{
    const float* x    = (const float*)d_in[0];
    const float* mask0= (const float*)d_in[1];
    const float* Wq   = (const float*)d_in[2];
    const float* bq   = (const float*)d_in[3];
    const float* Wk   = (const float*)d_in[4];
    const float* bk   = (const float*)d_in[5];
    const float* Wv   = (const float*)d_in[6];
    const float* bv   = (const float*)d_in[7];
    const float* Wo   = (const float*)d_in[8];
    const float* bo   = (const float*)d_in[9];
    const float* lng  = (const float*)d_in[10];
    const float* lnb  = (const float*)d_in[11];
    float* out = (float*)d_out;

    cudaFuncSetAttribute(k_qkv, cudaFuncAttributeMaxDynamicSharedMemorySize, GEMM_SMEM);
    cudaFuncSetAttribute(k_out, cudaFuncAttributeMaxDynamicSharedMemorySize, GEMM_SMEM);

    k_split_w<<<144, 256>>>(Wq, Wk, Wv, Wo);
    k_qkv<<<MTOT / 128, 256, GEMM_SMEM>>>(x, bq, bk, bv);
    k_attn<<<(MTOT * NH) / 256, 256>>>(mask0);
    k_out<<<MTOT / 128, 256, GEMM_SMEM>>>(x, bo, lng, lnb, out);
}